// round 15
// baseline (speedup 1.0000x reference)
#include <cuda_runtime.h>
#include <cstdint>

// BATCH=16384, NCONDS=50, EMB=64, table rows=100002
// d_in[0]: int32 input [B,51]   d_in[1]: float table [100002,64]
// out: float [B, 64 + 50*64]

constexpr int EMB     = 64;
constexpr int NCONDS  = 50;
constexpr int ROW_IN  = 1 + NCONDS;           // 51
constexpr int ROW_OUT = EMB + NCONDS * EMB;   // 3264

constexpr int NR      = 4;                    // rows per block
constexpr int THREADS = 256;                  // 8 warps: 2 warps per row
constexpr int EMB4    = EMB / 4;              // 16 float4 per embedding
constexpr int SLOTS   = ROW_IN;               // 51 embeddings per row (event + 50 conds)
constexpr int SMEM_EMB_FLOATS = NR * SLOTS * EMB;          // 13056 floats = 52224 B
constexpr int SMEM_BYTES      = SMEM_EMB_FLOATS * 4 + NR * SLOTS * 4 + 16; // + indices

__global__ __launch_bounds__(THREADS) void cond_filter_kernel(
    const int*   __restrict__ inp,
    const float* __restrict__ table,
    float*       __restrict__ out,
    int batch)
{
    extern __shared__ float smem[];
    float* s_emb = smem;                                   // [NR][51][64]
    int*   s_idx = reinterpret_cast<int*>(smem + SMEM_EMB_FLOATS); // [NR*51]

    const unsigned FULL = 0xffffffffu;
    const int tid  = threadIdx.x;
    const int row0 = blockIdx.x * NR;

    // ---- Phase 1a: stage indices (contiguous across the block's 4 rows) ----
    for (int t = tid; t < NR * SLOTS; t += THREADS) {
        const int r = t / SLOTS;
        const int j = t - r * SLOTS;
        const int grow = min(row0 + r, batch - 1);   // clamp (dup work, same values)
        s_idx[t] = __ldg(inp + (long)grow * ROW_IN + j);
    }
    __syncthreads();

    // ---- Phase 1b: bulk gather — 3264 independent LDG.128 per block (~13/thread) ----
    float4* s_emb4 = reinterpret_cast<float4*>(s_emb);
    #pragma unroll 1
    for (int u = tid; u < NR * SLOTS * EMB4; u += THREADS) {
        const int slot = u >> 4;            // u / EMB4 (EMB4 == 16)
        const int q    = u & 15;
        const int idx  = s_idx[slot];
        s_emb4[u] = *reinterpret_cast<const float4*>(table + (long)idx * EMB + 4 * q);
    }
    __syncthreads();

    // ---- Phase 2: compute from smem ----
    const int wid  = tid >> 5;
    const int lane = tid & 31;
    const int r    = wid >> 1;        // row within block (0..3)
    const int sub  = wid & 1;         // 0: conds 0..24, 1: conds 25..49
    const int half = lane >> 4;       // which cond of the current pair
    const int hl   = lane & 15;       // float4 slot within embedding

    const int grow = min(row0 + r, batch - 1);
    float* orow = out + (long)grow * ROW_OUT;

    // event embedding (slot 0 of this row); both halves read the same 64 floats
    const float* eemb = s_emb + (long)r * SLOTS * EMB;
    const float4 ev = *reinterpret_cast<const float4*>(eemb + 4 * hl);

    if (sub == 0 && half == 0)   // one warp-half writes the raw event embedding
        __stcs(reinterpret_cast<float4*>(orow + 4 * hl), ev);

    float ss = ev.x * ev.x + ev.y * ev.y + ev.z * ev.z + ev.w * ev.w;
    #pragma unroll
    for (int o = 8; o; o >>= 1) ss += __shfl_xor_sync(FULL, ss, o);
    const float rinv = rsqrtf(ss);
    const float enx = ev.x * rinv, eny = ev.y * rinv;
    const float enz = ev.z * rinv, enw = ev.w * rinv;

    // 25 conds per warp, 2 per iteration; 13 iterations, last one clamps
    // (both halves then compute/store identical values for cond 24 of the range)
    #pragma unroll 1
    for (int i = 0; i < 13; ++i) {
        const int cl   = min(i * 2 + half, 24);
        const int cond = sub * 25 + cl;

        const float4 a = *reinterpret_cast<const float4*>(
            s_emb + ((long)r * SLOTS + 1 + cond) * EMB + 4 * hl);

        float p = enx * a.x + eny * a.y + enz * a.z + enw * a.w;   // dot(e_n, c)
        float q = a.x * a.x + a.y * a.y + a.z * a.z + a.w * a.w;   // dot(c, c)
        #pragma unroll
        for (int o = 8; o; o >>= 1) {
            p += __shfl_xor_sync(FULL, p, o);
            q += __shfl_xor_sync(FULL, q, o);
        }

        const float s = __fdividef(p, q);
        float4 w;
        w.x = a.x * s; w.y = a.y * s; w.z = a.z * s; w.w = a.w * s;
        __stcs(reinterpret_cast<float4*>(orow + EMB + (long)cond * EMB + 4 * hl), w);
    }
}

extern "C" void kernel_launch(void* const* d_in, const int* in_sizes, int n_in,
                              void* d_out, int out_size)
{
    const int*   inp   = (const int*)d_in[0];
    const float* table = (const float*)d_in[1];
    float*       out   = (float*)d_out;

    const int batch  = in_sizes[0] / ROW_IN;
    const int blocks = (batch + NR - 1) / NR;

    // >48KB dynamic smem requires the opt-in attribute (idempotent, not a
    // stream op — safe under graph capture).
    cudaFuncSetAttribute(cond_filter_kernel,
                         cudaFuncAttributeMaxDynamicSharedMemorySize, SMEM_BYTES);

    cond_filter_kernel<<<blocks, THREADS, SMEM_BYTES>>>(inp, table, out, batch);
}